// round 7
// baseline (speedup 1.0000x reference)
#include <cuda_runtime.h>
#include <cuda_fp16.h>
#include <cstdint>

#define IN_CH   256
#define OUT_CH  256
#define HID     128
#define S_MAX   16384

// smem geometry
#define SA2       264         // resident A tile stride (256 k + 8 pad), fp16
#define SBS       136         // B stream tile stride (128 n + 8 pad), fp16
#define A_ELEMS   33792       // 128*264
#define BBUF      4352        // 32*136 fp16 per stream buffer
#define BSTR_OFF  33792       // elems
#define STG_OFF_B 84992       // bytes: (33792 + 2*4352)*2
#define TSST      133         // fp32 staging stride
#define SMEM_BYTES 153088     // 84992 + 128*133*4

// ---------------- scratch (device globals: no allocation allowed) ----------
__device__ float g_segsum[S_MAX];
__device__ int   g_idx64;
__device__ __align__(16) __half g_W1h[IN_CH * HID];
__device__ __align__(16) __half g_Wth[IN_CH * OUT_CH];

// ---------------- helpers ---------------------------------------------------
__device__ __forceinline__ int load_idx(const void* idx, int i) {
    if (g_idx64) return (int)((const long long*)idx)[i];
    return ((const int*)idx)[i];
}

#define LDSM4(R, ADDR)                                                        \
    asm volatile("ldmatrix.sync.aligned.m8n8.x4.shared.b16 {%0,%1,%2,%3},[%4];" \
                 : "=r"(R[0]), "=r"(R[1]), "=r"(R[2]), "=r"(R[3]) : "r"(ADDR))
#define LDSM4T(R, ADDR)                                                       \
    asm volatile("ldmatrix.sync.aligned.m8n8.x4.trans.shared.b16 {%0,%1,%2,%3},[%4];" \
                 : "=r"(R[0]), "=r"(R[1]), "=r"(R[2]), "=r"(R[3]) : "r"(ADDR))
#define MMA_F16(C, A, B0, B1)                                                 \
    asm volatile("mma.sync.aligned.m16n8k16.row.col.f32.f16.f16.f32 "         \
                 "{%0,%1,%2,%3},{%4,%5,%6,%7},{%8,%9},{%0,%1,%2,%3};"         \
                 : "+f"(C[0]), "+f"(C[1]), "+f"(C[2]), "+f"(C[3])             \
                 : "r"(A[0]), "r"(A[1]), "r"(A[2]), "r"(A[3]),                \
                   "r"(B0), "r"(B1))

// ---------------- tiny kernels ----------------------------------------------
__global__ void detect_idx_kernel(const void* __restrict__ idx, int n) {
    if (threadIdx.x == 0 && blockIdx.x == 0) {
        const long long* p = (const long long*)idx;
        int base = n / 4;
        int ok64 = 1;
        for (int i = 0; i < 8; i++) {
            long long v = p[base + i];
            if (v < 0 || v >= (1LL << 31)) ok64 = 0;
        }
        g_idx64 = ok64;
    }
}

__global__ void init_seg_kernel() {
    int s = blockIdx.x * blockDim.x + threadIdx.x;
    if (s < S_MAX) g_segsum[s] = 0.f;
}

__global__ void convert_w_kernel(const float* __restrict__ W1,
                                 const float* __restrict__ Wt) {
    int i = blockIdx.x * blockDim.x + threadIdx.x;
    if (i < IN_CH * OUT_CH) g_Wth[i] = __float2half_rn(Wt[i]);
    if (i < IN_CH * HID)    g_W1h[i] = __float2half_rn(W1[i]);
}

// out[s][c] /= max(segsum[s], 1e-16)  (empty segments stay 0)
__global__ void norm_kernel(float* __restrict__ out, int total) {
    int i = blockIdx.x * blockDim.x + threadIdx.x;
    if (i < total) out[i] /= fmaxf(g_segsum[i >> 8], 1e-16f);
}

// ---------------- fused kernel: X read ONCE per tile -------------------------
// 1) X tile -> resident fp16 A smem
// 2) gate GEMM (W1 streamed) -> shuffle-reduce -> e=exp(gate), segsum atomics
// 3) transform GEMM, two N-halves (Wt streamed), A reused from smem
// 4) sorted segmented column scan scattering UNNORMALIZED e*t (divide later)
__global__ __launch_bounds__(256, 1) void fused_kernel(
    const float* __restrict__ X, const void* __restrict__ idx,
    const float* __restrict__ b1, const float* __restrict__ W2,
    const float* __restrict__ b2, const float* __restrict__ bt,
    float* __restrict__ out, int n)
{
    extern __shared__ __half sm[];
    __shared__ float red[256];      // [row][colgroup]: 128 x 2
    __shared__ int   sidx[128];
    __shared__ float se[128];
    __shared__ float sb1[128];
    __shared__ float sw2[128];

    const int tid  = threadIdx.x;
    const int lane = tid & 31;
    const int warp = tid >> 5;
    const int warpRow = (warp & 3) * 32;
    const int warpCol = (warp >> 2) * 64;
    const int rowBase = blockIdx.x * 128;

    const uint32_t smemBase = (uint32_t)__cvta_generic_to_shared(sm);
    float* Tsm = (float*)((char*)sm + STG_OFF_B);

    if (tid < 128) { sb1[tid] = b1[tid]; sw2[tid] = W2[tid]; }

    // ---- 1) load X tile once, convert fp16, store resident ----
#pragma unroll 4
    for (int j = 0; j < 32; j++) {
        int f   = j * 256 + tid;            // 8192 float4s
        int row = f >> 6, q = f & 63;       // 64 float4 per row
        int gr  = rowBase + row;
        float4 v = (gr < n)
            ? __ldg((const float4*)(X + (size_t)gr * IN_CH + q * 4))
            : make_float4(0.f, 0.f, 0.f, 0.f);
        __half2 h0 = __floats2half2_rn(v.x, v.y);
        __half2 h1 = __floats2half2_rn(v.z, v.w);
        int off = row * SA2 + q * 4;
        *(uint2*)&sm[off] = make_uint2(*(uint32_t*)&h0, *(uint32_t*)&h1);
    }
    __syncthreads();

    // ---- B-stream + compute machinery ----
    auto cpB = [&](int buf, int kt, const __half* src, int ldb, int colBase) {
#pragma unroll
        for (int u = 0; u < 2; u++) {
            int e = tid + 256 * u;
            int krow = e >> 4, c16 = e & 15;
            const __half* s =
                src + (size_t)(kt * 32 + krow) * ldb + colBase + c16 * 8;
            uint32_t dst = smemBase +
                (uint32_t)(BSTR_OFF + buf * BBUF + krow * SBS + c16 * 8) * 2u;
            asm volatile("cp.async.ca.shared.global [%0],[%1],16;\n"
                         :: "r"(dst), "l"(__cvta_generic_to_global(s)));
        }
    };
    auto computeChunk = [&](int buf, int kt, float (&acc)[2][8][4]) {
#pragma unroll
        for (int kk = 0; kk < 32; kk += 16) {
            uint32_t ah[2][4];
#pragma unroll
            for (int mt = 0; mt < 2; mt++) {
                int row = warpRow + mt * 16 + (lane & 15);
                int k   = kt * 32 + kk + ((lane >> 4) << 3);
                LDSM4(ah[mt], smemBase + (uint32_t)(row * SA2 + k) * 2u);
            }
#pragma unroll
            for (int p = 0; p < 4; p++) {
                int krow = kk + (lane & 7) + (((lane >> 3) & 1) << 3);
                int ncol = warpCol + p * 16 + ((lane >> 4) << 3);
                uint32_t bh[4];
                LDSM4T(bh, smemBase +
                    (uint32_t)(BSTR_OFF + buf * BBUF + krow * SBS + ncol) * 2u);
                MMA_F16(acc[0][2 * p],     ah[0], bh[0], bh[1]);
                MMA_F16(acc[1][2 * p],     ah[1], bh[0], bh[1]);
                MMA_F16(acc[0][2 * p + 1], ah[0], bh[2], bh[3]);
                MMA_F16(acc[1][2 * p + 1], ah[1], bh[2], bh[3]);
            }
        }
    };
    auto gemmPhase = [&](const __half* Bsrc, int ldb, int colBase,
                         float (&acc)[2][8][4]) {
        cpB(0, 0, Bsrc, ldb, colBase);
        asm volatile("cp.async.commit_group;");
        asm volatile("cp.async.wait_group 0;");
        __syncthreads();
#pragma unroll 1
        for (int kt = 0; kt < 8; kt++) {
            int cur = kt & 1;
            bool more = (kt < 7);
            if (more) {
                cpB(1 - cur, kt + 1, Bsrc, ldb, colBase);
                asm volatile("cp.async.commit_group;");
            }
            computeChunk(cur, kt, acc);
            if (more) asm volatile("cp.async.wait_group 0;");
            __syncthreads();
        }
    };

    // ---- 2) gate GEMM + fused softmax-numerator ----
    {
        float acc[2][8][4];
#pragma unroll
        for (int mt = 0; mt < 2; mt++)
#pragma unroll
            for (int nt = 0; nt < 8; nt++)
#pragma unroll
                for (int q = 0; q < 4; q++) acc[mt][nt][q] = 0.f;

        gemmPhase(g_W1h, HID, 0, acc);

        // relu(+b1)·W2 partial per thread, shuffle-reduce over 4-lane groups
#pragma unroll
        for (int mt = 0; mt < 2; mt++) {
            float p0 = 0.f, p1 = 0.f;
#pragma unroll
            for (int nt = 0; nt < 8; nt++) {
                int c0 = warpCol + nt * 8 + ((lane & 3) << 1);
                p0 += fmaxf(acc[mt][nt][0] + sb1[c0],     0.f) * sw2[c0];
                p0 += fmaxf(acc[mt][nt][1] + sb1[c0 + 1], 0.f) * sw2[c0 + 1];
                p1 += fmaxf(acc[mt][nt][2] + sb1[c0],     0.f) * sw2[c0];
                p1 += fmaxf(acc[mt][nt][3] + sb1[c0 + 1], 0.f) * sw2[c0 + 1];
            }
            p0 += __shfl_xor_sync(0xffffffffu, p0, 1);
            p0 += __shfl_xor_sync(0xffffffffu, p0, 2);
            p1 += __shfl_xor_sync(0xffffffffu, p1, 1);
            p1 += __shfl_xor_sync(0xffffffffu, p1, 2);
            if ((lane & 3) == 0) {
                int r = warpRow + mt * 16 + (lane >> 2);
                red[r * 2 + (warp >> 2)]       = p0;
                red[(r + 8) * 2 + (warp >> 2)] = p1;
            }
        }
        __syncthreads();
        if (tid < 128) {
            int gr = rowBase + tid;
            if (gr < n) {
                float g = b2[0] + red[tid * 2] + red[tid * 2 + 1];
                float e = expf(g);      // gate is O(1): no max-shift needed
                se[tid] = e;
                int s = load_idx(idx, gr);
                sidx[tid] = s;
                atomicAdd(&g_segsum[s], e);
            } else { sidx[tid] = -1; se[tid] = 0.f; }
        }
        // gemmPhase's internal syncs + the one below order se/sidx for scatter
    }

    // ---- 3)+4) transform GEMM per N-half, scatter unnormalized e*t ----
#pragma unroll 1
    for (int h = 0; h < 2; h++) {
        float acc[2][8][4];
#pragma unroll
        for (int mt = 0; mt < 2; mt++)
#pragma unroll
            for (int nt = 0; nt < 8; nt++)
#pragma unroll
                for (int q = 0; q < 4; q++) acc[mt][nt][q] = 0.f;

        gemmPhase(g_Wth, OUT_CH, h * 128, acc);

        // stage to fp32 smem
#pragma unroll
        for (int mt = 0; mt < 2; mt++)
#pragma unroll
            for (int nt = 0; nt < 8; nt++) {
                int r0 = warpRow + mt * 16 + (lane >> 2);
                int c0 = warpCol + nt * 8 + ((lane & 3) << 1);
                Tsm[r0 * TSST + c0]           = acc[mt][nt][0];
                Tsm[r0 * TSST + c0 + 1]       = acc[mt][nt][1];
                Tsm[(r0 + 8) * TSST + c0]     = acc[mt][nt][2];
                Tsm[(r0 + 8) * TSST + c0 + 1] = acc[mt][nt][3];
            }
        __syncthreads();

        // sorted segmented column scan: weight = e (unnormalized)
        {
            int c = tid & 127;
            int rStart = (tid >> 7) * 64;
            float btc = __ldg(bt + h * 128 + c);
            float a = 0.f;
            int prev = -1;
            for (int r = rStart; r < rStart + 64; r++) {
                int s = sidx[r];
                if (s < 0) break;
                if (s != prev) {
                    if (prev >= 0)
                        atomicAdd(&out[(size_t)prev * OUT_CH + h * 128 + c], a);
                    a = 0.f;
                    prev = s;
                }
                a = fmaf(fmaxf(Tsm[r * TSST + c] + btc, 0.f), se[r], a);
            }
            if (prev >= 0)
                atomicAdd(&out[(size_t)prev * OUT_CH + h * 128 + c], a);
        }
        __syncthreads();    // staging reused by next half
    }
}

// ---------------- launch -----------------------------------------------------
extern "C" void kernel_launch(void* const* d_in, const int* in_sizes, int n_in,
                              void* d_out, int out_size)
{
    const float* X   = (const float*)d_in[0];
    const void*  idx = d_in[1];
    int base = (n_in >= 9 && in_sizes[2] <= 16) ? 3 : 2;
    const float* W1 = (const float*)d_in[base + 0];
    const float* b1 = (const float*)d_in[base + 1];
    const float* W2 = (const float*)d_in[base + 2];
    const float* b2 = (const float*)d_in[base + 3];
    const float* Wt = (const float*)d_in[base + 4];
    const float* bt = (const float*)d_in[base + 5];

    const int n = in_sizes[0] / IN_CH;
    float* out = (float*)d_out;

    cudaFuncSetAttribute(fused_kernel,
                         cudaFuncAttributeMaxDynamicSharedMemorySize, SMEM_BYTES);

    cudaMemsetAsync(d_out, 0, (size_t)out_size * sizeof(float), 0);
    detect_idx_kernel<<<1, 32>>>(idx, n);
    init_seg_kernel<<<(S_MAX + 255) / 256, 256>>>();
    convert_w_kernel<<<(IN_CH * OUT_CH + 255) / 256, 256>>>(W1, Wt);

    const int nTiles = (n + 127) / 128;
    fused_kernel<<<nTiles, 256, SMEM_BYTES>>>(
        X, idx, b1, W2, b2, bt, out, n);
    norm_kernel<<<(out_size + 255) / 256, 256>>>(out, out_size);
}

// round 8
// speedup vs baseline: 1.2128x; 1.2128x over previous
#include <cuda_runtime.h>
#include <cuda_fp16.h>
#include <cstdint>

#define IN_CH   256
#define OUT_CH  256
#define HID     128
#define S_MAX   16384

// smem geometry
#define SA2       264         // resident A tile stride (256 k + 8 pad), fp16
#define SBS       136         // B stream tile stride (128 n + 8 pad), fp16
#define BBUF      4352        // 32*136 fp16 per stream buffer
#define BSTR_OFF  33792       // elems (128*264)
#define STG_OFF_B 84992       // bytes: (33792 + 2*4352)*2
#define TSST      133         // fp32 staging stride
#define SMEM_BYTES 153088     // 84992 + 128*133*4

// ---------------- scratch (device globals: no allocation allowed) ----------
__device__ float g_segsum[S_MAX];
__device__ int   g_idx64;
__device__ __align__(16) __half g_W1h[IN_CH * HID];
__device__ __align__(16) __half g_Wth[IN_CH * OUT_CH];

// ---------------- helpers ---------------------------------------------------
__device__ __forceinline__ int load_idx(const void* idx, int i) {
    if (g_idx64) return (int)((const long long*)idx)[i];
    return ((const int*)idx)[i];
}

#define LDSM4(R, ADDR)                                                        \
    asm volatile("ldmatrix.sync.aligned.m8n8.x4.shared.b16 {%0,%1,%2,%3},[%4];" \
                 : "=r"(R[0]), "=r"(R[1]), "=r"(R[2]), "=r"(R[3]) : "r"(ADDR))
#define LDSM4T(R, ADDR)                                                       \
    asm volatile("ldmatrix.sync.aligned.m8n8.x4.trans.shared.b16 {%0,%1,%2,%3},[%4];" \
                 : "=r"(R[0]), "=r"(R[1]), "=r"(R[2]), "=r"(R[3]) : "r"(ADDR))
#define MMA_F16(C, A, B0, B1)                                                 \
    asm volatile("mma.sync.aligned.m16n8k16.row.col.f32.f16.f16.f32 "         \
                 "{%0,%1,%2,%3},{%4,%5,%6,%7},{%8,%9},{%0,%1,%2,%3};"         \
                 : "+f"(C[0]), "+f"(C[1]), "+f"(C[2]), "+f"(C[3])             \
                 : "r"(A[0]), "r"(A[1]), "r"(A[2]), "r"(A[3]),                \
                   "r"(B0), "r"(B1))

// ---------------- tiny kernels ----------------------------------------------
__global__ void detect_idx_kernel(const void* __restrict__ idx, int n) {
    if (threadIdx.x == 0 && blockIdx.x == 0) {
        const long long* p = (const long long*)idx;
        int base = n / 4;
        int ok64 = 1;
        for (int i = 0; i < 8; i++) {
            long long v = p[base + i];
            if (v < 0 || v >= (1LL << 31)) ok64 = 0;
        }
        g_idx64 = ok64;
    }
}

__global__ void init_seg_kernel() {
    int s = blockIdx.x * blockDim.x + threadIdx.x;
    if (s < S_MAX) g_segsum[s] = 0.f;
}

__global__ void convert_w_kernel(const float* __restrict__ W1,
                                 const float* __restrict__ Wt) {
    int i = blockIdx.x * blockDim.x + threadIdx.x;
    if (i < IN_CH * OUT_CH) g_Wth[i] = __float2half_rn(Wt[i]);
    if (i < IN_CH * HID)    g_W1h[i] = __float2half_rn(W1[i]);
}

// out[s][c] /= max(segsum[s], 1e-16)  (empty segments stay 0)
__global__ void norm_kernel(float* __restrict__ out, int total) {
    int i = blockIdx.x * blockDim.x + threadIdx.x;
    if (i < total) out[i] /= fmaxf(g_segsum[i >> 8], 1e-16f);
}

// ---------------- fused kernel: X read ONCE, 512 threads / 16 warps ---------
// warp grid 4x4: warpRow = (warp&3)*32, warpCol = (warp>>2)*32; tile 32x32.
__global__ __launch_bounds__(512, 1) void fused_kernel(
    const float* __restrict__ X, const void* __restrict__ idx,
    const float* __restrict__ b1, const float* __restrict__ W2,
    const float* __restrict__ b2, const float* __restrict__ bt,
    float* __restrict__ out, int n)
{
    extern __shared__ __half sm[];
    __shared__ float red[512];      // [row][colgroup]: 128 x 4
    __shared__ int   sidx[128];
    __shared__ float se[128];
    __shared__ float sb1[128];
    __shared__ float sw2[128];

    const int tid  = threadIdx.x;
    const int lane = tid & 31;
    const int warp = tid >> 5;
    const int warpRow = (warp & 3) * 32;
    const int warpCol = (warp >> 2) * 32;
    const int rowBase = blockIdx.x * 128;

    const uint32_t smemBase = (uint32_t)__cvta_generic_to_shared(sm);
    float* Tsm = (float*)((char*)sm + STG_OFF_B);

    if (tid < 128) { sb1[tid] = b1[tid]; sw2[tid] = W2[tid]; }

    // ---- 1) load X tile once, convert fp16, store resident ----
#pragma unroll 4
    for (int j = 0; j < 16; j++) {
        int f   = j * 512 + tid;            // 8192 float4s
        int row = f >> 6, q = f & 63;
        int gr  = rowBase + row;
        float4 v = (gr < n)
            ? __ldg((const float4*)(X + (size_t)gr * IN_CH + q * 4))
            : make_float4(0.f, 0.f, 0.f, 0.f);
        __half2 h0 = __floats2half2_rn(v.x, v.y);
        __half2 h1 = __floats2half2_rn(v.z, v.w);
        int off = row * SA2 + q * 4;
        *(uint2*)&sm[off] = make_uint2(*(uint32_t*)&h0, *(uint32_t*)&h1);
    }
    __syncthreads();

    // ---- B-stream + compute machinery ----
    auto cpB = [&](int buf, int kt, const __half* src, int ldb, int colBase) {
        int krow = tid >> 4, c16 = tid & 15;      // 512 = 32 x 16 granules
        const __half* s =
            src + (size_t)(kt * 32 + krow) * ldb + colBase + c16 * 8;
        uint32_t dst = smemBase +
            (uint32_t)(BSTR_OFF + buf * BBUF + krow * SBS + c16 * 8) * 2u;
        asm volatile("cp.async.ca.shared.global [%0],[%1],16;\n"
                     :: "r"(dst), "l"(__cvta_generic_to_global(s)));
    };
    auto computeChunk = [&](int buf, int kt, float (&acc)[2][4][4]) {
#pragma unroll
        for (int kk = 0; kk < 32; kk += 16) {
            uint32_t ah[2][4];
#pragma unroll
            for (int mt = 0; mt < 2; mt++) {
                int row = warpRow + mt * 16 + (lane & 15);
                int k   = kt * 32 + kk + ((lane >> 4) << 3);
                LDSM4(ah[mt], smemBase + (uint32_t)(row * SA2 + k) * 2u);
            }
#pragma unroll
            for (int p = 0; p < 2; p++) {
                int krow = kk + (lane & 7) + (((lane >> 3) & 1) << 3);
                int ncol = warpCol + p * 16 + ((lane >> 4) << 3);
                uint32_t bh[4];
                LDSM4T(bh, smemBase +
                    (uint32_t)(BSTR_OFF + buf * BBUF + krow * SBS + ncol) * 2u);
                MMA_F16(acc[0][2 * p],     ah[0], bh[0], bh[1]);
                MMA_F16(acc[1][2 * p],     ah[1], bh[0], bh[1]);
                MMA_F16(acc[0][2 * p + 1], ah[0], bh[2], bh[3]);
                MMA_F16(acc[1][2 * p + 1], ah[1], bh[2], bh[3]);
            }
        }
    };
    auto gemmPhase = [&](const __half* Bsrc, int ldb, int colBase,
                         float (&acc)[2][4][4]) {
        cpB(0, 0, Bsrc, ldb, colBase);
        asm volatile("cp.async.commit_group;");
        asm volatile("cp.async.wait_group 0;");
        __syncthreads();
#pragma unroll 1
        for (int kt = 0; kt < 8; kt++) {
            int cur = kt & 1;
            bool more = (kt < 7);
            if (more) {
                cpB(1 - cur, kt + 1, Bsrc, ldb, colBase);
                asm volatile("cp.async.commit_group;");
            }
            computeChunk(cur, kt, acc);
            if (more) asm volatile("cp.async.wait_group 0;");
            __syncthreads();
        }
    };

    // ---- 2) gate GEMM + fused softmax-numerator ----
    {
        float acc[2][4][4];
#pragma unroll
        for (int mt = 0; mt < 2; mt++)
#pragma unroll
            for (int nt = 0; nt < 4; nt++)
#pragma unroll
                for (int q = 0; q < 4; q++) acc[mt][nt][q] = 0.f;

        gemmPhase(g_W1h, HID, 0, acc);

        // relu(+b1)·W2 partials over this warp's 32 cols, reduce lane quads
#pragma unroll
        for (int mt = 0; mt < 2; mt++) {
            float p0 = 0.f, p1 = 0.f;
#pragma unroll
            for (int nt = 0; nt < 4; nt++) {
                int c0 = warpCol + nt * 8 + ((lane & 3) << 1);
                p0 += fmaxf(acc[mt][nt][0] + sb1[c0],     0.f) * sw2[c0];
                p0 += fmaxf(acc[mt][nt][1] + sb1[c0 + 1], 0.f) * sw2[c0 + 1];
                p1 += fmaxf(acc[mt][nt][2] + sb1[c0],     0.f) * sw2[c0];
                p1 += fmaxf(acc[mt][nt][3] + sb1[c0 + 1], 0.f) * sw2[c0 + 1];
            }
            p0 += __shfl_xor_sync(0xffffffffu, p0, 1);
            p0 += __shfl_xor_sync(0xffffffffu, p0, 2);
            p1 += __shfl_xor_sync(0xffffffffu, p1, 1);
            p1 += __shfl_xor_sync(0xffffffffu, p1, 2);
            if ((lane & 3) == 0) {
                int r = warpRow + mt * 16 + (lane >> 2);
                red[r * 4 + (warp >> 2)]       = p0;
                red[(r + 8) * 4 + (warp >> 2)] = p1;
            }
        }
        __syncthreads();
        if (tid < 128) {
            int gr = rowBase + tid;
            if (gr < n) {
                float g = b2[0] + (red[tid * 4] + red[tid * 4 + 1])
                                + (red[tid * 4 + 2] + red[tid * 4 + 3]);
                float e = expf(g);      // gate is O(1): no max-shift needed
                se[tid] = e;
                int s = load_idx(idx, gr);
                sidx[tid] = s;
                atomicAdd(&g_segsum[s], e);
            } else { sidx[tid] = -1; se[tid] = 0.f; }
        }
    }

    // ---- 3)+4) transform GEMM per N-half, scatter unnormalized e*t ----
#pragma unroll 1
    for (int h = 0; h < 2; h++) {
        float acc[2][4][4];
#pragma unroll
        for (int mt = 0; mt < 2; mt++)
#pragma unroll
            for (int nt = 0; nt < 4; nt++)
#pragma unroll
                for (int q = 0; q < 4; q++) acc[mt][nt][q] = 0.f;

        gemmPhase(g_Wth, OUT_CH, h * 128, acc);

        // stage to fp32 smem
#pragma unroll
        for (int mt = 0; mt < 2; mt++)
#pragma unroll
            for (int nt = 0; nt < 4; nt++) {
                int r0 = warpRow + mt * 16 + (lane >> 2);
                int c0 = warpCol + nt * 8 + ((lane & 3) << 1);
                Tsm[r0 * TSST + c0]           = acc[mt][nt][0];
                Tsm[r0 * TSST + c0 + 1]       = acc[mt][nt][1];
                Tsm[(r0 + 8) * TSST + c0]     = acc[mt][nt][2];
                Tsm[(r0 + 8) * TSST + c0 + 1] = acc[mt][nt][3];
            }
        __syncthreads();

        // sorted segmented column scan: 128 cols x 4 row-quarters (32 rows)
        {
            int c = tid & 127;
            int rStart = (tid >> 7) * 32;
            float btc = __ldg(bt + h * 128 + c);
            float a = 0.f;
            int prev = -1;
            for (int r = rStart; r < rStart + 32; r++) {
                int s = sidx[r];
                if (s < 0) break;
                if (s != prev) {
                    if (prev >= 0)
                        atomicAdd(&out[(size_t)prev * OUT_CH + h * 128 + c], a);
                    a = 0.f;
                    prev = s;
                }
                a = fmaf(fmaxf(Tsm[r * TSST + c] + btc, 0.f), se[r], a);
            }
            if (prev >= 0)
                atomicAdd(&out[(size_t)prev * OUT_CH + h * 128 + c], a);
        }
        __syncthreads();    // staging reused by next half
    }
}

// ---------------- launch -----------------------------------------------------
extern "C" void kernel_launch(void* const* d_in, const int* in_sizes, int n_in,
                              void* d_out, int out_size)
{
    const float* X   = (const float*)d_in[0];
    const void*  idx = d_in[1];
    int base = (n_in >= 9 && in_sizes[2] <= 16) ? 3 : 2;
    const float* W1 = (const float*)d_in[base + 0];
    const float* b1 = (const float*)d_in[base + 1];
    const float* W2 = (const float*)d_in[base + 2];
    const float* b2 = (const float*)d_in[base + 3];
    const float* Wt = (const float*)d_in[base + 4];
    const float* bt = (const float*)d_in[base + 5];

    const int n = in_sizes[0] / IN_CH;
    float* out = (float*)d_out;

    cudaFuncSetAttribute(fused_kernel,
                         cudaFuncAttributeMaxDynamicSharedMemorySize, SMEM_BYTES);

    cudaMemsetAsync(d_out, 0, (size_t)out_size * sizeof(float), 0);
    detect_idx_kernel<<<1, 32>>>(idx, n);
    init_seg_kernel<<<(S_MAX + 255) / 256, 256>>>();
    convert_w_kernel<<<(IN_CH * OUT_CH + 255) / 256, 256>>>(W1, Wt);

    const int nTiles = (n + 127) / 128;
    fused_kernel<<<nTiles, 512, SMEM_BYTES>>>(
        X, idx, b1, W2, b2, bt, out, n);
    norm_kernel<<<(out_size + 255) / 256, 256>>>(out, out_size);
}

// round 9
// speedup vs baseline: 1.2926x; 1.0658x over previous
#include <cuda_runtime.h>
#include <cuda_fp16.h>
#include <cstdint>

#define IN_CH   256
#define OUT_CH  256
#define HID     128
#define S_MAX   16384
#define N_MAX   1100000

// smem geometry (fp16 element units)
#define SA      40            // A tile stride (32 k + 8 pad)
#define SB      136           // B tile stride (128 n + 8 pad)
#define TSST    133           // epilogue fp32 staging stride
#define A_OFF   0
#define B_OFF   5120          // 128*40
#define BUF_ELEMS 9472        // 5120 + 32*136 fp16 per pipeline buffer
#define SMEM_BYTES 68096      // max(2*9472*2, 128*133*4) = staging dominates

// ---------------- scratch (device globals: no allocation allowed) ----------
__device__ float g_e[N_MAX];
__device__ float g_segsum[S_MAX];
__device__ int   g_idx64;
// X converted to fp16 by the gate kernel; consumed by the transform kernel
__device__ __align__(16) __half g_Xh[(size_t)N_MAX * IN_CH];
// weights [k][n] row-major, single fp16 copy
__device__ __align__(16) __half g_W1h[IN_CH * HID];
__device__ __align__(16) __half g_Wth[IN_CH * OUT_CH];

// ---------------- helpers ---------------------------------------------------
__device__ __forceinline__ int load_idx(const void* idx, int i) {
    if (g_idx64) return (int)((const long long*)idx)[i];
    return ((const int*)idx)[i];
}

#define LDSM4(R, ADDR)                                                        \
    asm volatile("ldmatrix.sync.aligned.m8n8.x4.shared.b16 {%0,%1,%2,%3},[%4];" \
                 : "=r"(R[0]), "=r"(R[1]), "=r"(R[2]), "=r"(R[3]) : "r"(ADDR))
#define LDSM4T(R, ADDR)                                                       \
    asm volatile("ldmatrix.sync.aligned.m8n8.x4.trans.shared.b16 {%0,%1,%2,%3},[%4];" \
                 : "=r"(R[0]), "=r"(R[1]), "=r"(R[2]), "=r"(R[3]) : "r"(ADDR))
#define MMA_F16(C, A, B0, B1)                                                 \
    asm volatile("mma.sync.aligned.m16n8k16.row.col.f32.f16.f16.f32 "         \
                 "{%0,%1,%2,%3},{%4,%5,%6,%7},{%8,%9},{%0,%1,%2,%3};"         \
                 : "+f"(C[0]), "+f"(C[1]), "+f"(C[2]), "+f"(C[3])             \
                 : "r"(A[0]), "r"(A[1]), "r"(A[2]), "r"(A[3]),                \
                   "r"(B0), "r"(B1))

// ---------------- tiny kernels ----------------------------------------------
__global__ void detect_idx_kernel(const void* __restrict__ idx, int n) {
    if (threadIdx.x == 0 && blockIdx.x == 0) {
        const long long* p = (const long long*)idx;
        int base = n / 4;
        int ok64 = 1;
        for (int i = 0; i < 8; i++) {
            long long v = p[base + i];
            if (v < 0 || v >= (1LL << 31)) ok64 = 0;
        }
        g_idx64 = ok64;
    }
}

__global__ void init_seg_kernel() {
    int s = blockIdx.x * blockDim.x + threadIdx.x;
    if (s < S_MAX) g_segsum[s] = 0.f;
}

__global__ void convert_w_kernel(const float* __restrict__ W1,
                                 const float* __restrict__ Wt) {
    int i = blockIdx.x * blockDim.x + threadIdx.x;
    if (i < IN_CH * OUT_CH) g_Wth[i] = __float2half_rn(Wt[i]);
    if (i < IN_CH * HID)    g_W1h[i] = __float2half_rn(W1[i]);
}

// ---------------- main GEMM kernel (fp16 mma.sync) ---------------------------
// GATE=1: A from fp32 X (convert in regs, STS + STG fp16 scratch g_Xh).
//         C = X@W1; epilogue relu(+b1)·W2 + b2 -> gate, e = exp(gate),
//         store g_e, atomicAdd segment sum.
// GATE=0: A from fp16 g_Xh via cp.async (halved DRAM traffic, no converts).
//         C = X@Wt tile [128 of 256 cols]; relu(+bt)*alpha, sorted segmented
//         column scan + atomicAdd scatter.
template <int GATE>
__global__ __launch_bounds__(256, 2) void mma_gemm_kernel(
    const float* __restrict__ X, const void* __restrict__ idx,
    const float* __restrict__ bias,
    const float* __restrict__ W2, const float* __restrict__ b2,
    float* __restrict__ out, int n)
{
    extern __shared__ __half sm[];
    __shared__ int   sidx[128];
    __shared__ float srow[128];   // alpha (transform) / b1 (gate)
    __shared__ float sw2[128];    // W2 (gate only)

    const int tid  = threadIdx.x;
    const int lane = tid & 31;
    const int warp = tid >> 5;
    const int warpRow = (warp & 3) * 32;
    const int warpCol = (warp >> 2) * 64;
    const int rowBase = blockIdx.x * 128;
    const int nBase   = GATE ? 0 : (blockIdx.y * 128);
    const int ldB     = GATE ? HID : OUT_CH;
    const __half* __restrict__ Bg = GATE ? g_W1h : g_Wth;

    const uint32_t smemBase = (uint32_t)__cvta_generic_to_shared(sm);

    float acc[2][8][4];
#pragma unroll
    for (int mt = 0; mt < 2; mt++)
#pragma unroll
        for (int nt = 0; nt < 8; nt++)
#pragma unroll
            for (int q = 0; q < 4; q++) acc[mt][nt][q] = 0.f;

    float4 aPref[4];   // gate path only

    // ---- A fill: gate = LDG fp32 + convert + STS + STG scratch ----
    auto loadA = [&](int kt) {
#pragma unroll
        for (int u = 0; u < 4; u++) {
            int f = tid + 256 * u;
            int row = f >> 3, kq = f & 7;
            int gr = rowBase + row;
            aPref[u] = (gr < n)
                ? *(const float4*)(X + (size_t)gr * IN_CH + kt * 32 + kq * 4)
                : make_float4(0.f, 0.f, 0.f, 0.f);
        }
    };
    auto stsA = [&](int b, int kt) {
#pragma unroll
        for (int u = 0; u < 4; u++) {
            int f = tid + 256 * u;
            int row = f >> 3, kq = f & 7;
            float4 v = aPref[u];
            __half2 h0 = __floats2half2_rn(v.x, v.y);
            __half2 h1 = __floats2half2_rn(v.z, v.w);
            uint2 hp = make_uint2(*(uint32_t*)&h0, *(uint32_t*)&h1);
            int off = b * BUF_ELEMS + A_OFF + row * SA + kq * 4;
            *(uint2*)&sm[off] = hp;
            int gr = rowBase + row;
            if (gr < n)
                *(uint2*)&g_Xh[(size_t)gr * IN_CH + kt * 32 + kq * 4] = hp;
        }
    };
    // ---- A fill: transform = cp.async of fp16 scratch (16B granules) ----
    auto cpA = [&](int b, int kt) {
#pragma unroll
        for (int u = 0; u < 2; u++) {
            int g = tid + 256 * u;              // 512 granules: 128 rows x 4
            int row = g >> 2, kq = g & 3;       // kq covers 8 halves
            const __half* s =
                g_Xh + (size_t)(rowBase + row) * IN_CH + kt * 32 + kq * 8;
            uint32_t dst = smemBase +
                (uint32_t)(b * BUF_ELEMS + A_OFF + row * SA + kq * 8) * 2u;
            asm volatile("cp.async.ca.shared.global [%0],[%1],16;\n"
                         :: "r"(dst), "l"(__cvta_generic_to_global(s)));
        }
    };
    auto cpB = [&](int b, int kt) {
#pragma unroll
        for (int u = 0; u < 2; u++) {
            int e = tid + 256 * u;
            int krow = e >> 4, c16 = e & 15;
            const __half* src =
                Bg + (size_t)(kt * 32 + krow) * ldB + nBase + c16 * 8;
            uint32_t dst = smemBase +
                (uint32_t)(b * BUF_ELEMS + B_OFF + krow * SB + c16 * 8) * 2u;
            asm volatile("cp.async.ca.shared.global [%0],[%1],16;\n"
                         :: "r"(dst), "l"(__cvta_generic_to_global(src)));
        }
    };
    auto compute = [&](int b) {
#pragma unroll
        for (int kk = 0; kk < 32; kk += 16) {
            uint32_t ah[2][4];
#pragma unroll
            for (int mt = 0; mt < 2; mt++) {
                int row = warpRow + mt * 16 + (lane & 15);
                int kof = kk + ((lane >> 4) << 3);
                uint32_t ad = smemBase +
                    (uint32_t)(b * BUF_ELEMS + A_OFF + row * SA + kof) * 2u;
                LDSM4(ah[mt], ad);
            }
#pragma unroll
            for (int p = 0; p < 4; p++) {
                int krow = kk + (lane & 7) + (((lane >> 3) & 1) << 3);
                int ncol = warpCol + p * 16 + ((lane >> 4) << 3);
                uint32_t bA = smemBase +
                    (uint32_t)(b * BUF_ELEMS + B_OFF + krow * SB + ncol) * 2u;
                uint32_t bh[4];
                LDSM4T(bh, bA);
                MMA_F16(acc[0][2 * p],     ah[0], bh[0], bh[1]);
                MMA_F16(acc[1][2 * p],     ah[1], bh[0], bh[1]);
                MMA_F16(acc[0][2 * p + 1], ah[0], bh[2], bh[3]);
                MMA_F16(acc[1][2 * p + 1], ah[1], bh[2], bh[3]);
            }
        }
    };

    // ---- pipeline: 8 K-steps of 32 ----
    if (GATE) {
        loadA(0);
        cpB(0, 0);
        asm volatile("cp.async.commit_group;");
        stsA(0, 0);
        asm volatile("cp.async.wait_group 0;");
    } else {
        cpA(0, 0);
        cpB(0, 0);
        asm volatile("cp.async.commit_group;");
        asm volatile("cp.async.wait_group 0;");
    }
    __syncthreads();

#pragma unroll 1
    for (int kt = 0; kt < 8; kt++) {
        int cur = kt & 1;
        bool more = (kt < 7);
        if (more) {
            if (GATE) loadA(kt + 1);
            else      cpA(1 - cur, kt + 1);
            cpB(1 - cur, kt + 1);
            asm volatile("cp.async.commit_group;");
        }
        compute(cur);
        if (more) {
            if (GATE) stsA(1 - cur, kt + 1);
            asm volatile("cp.async.wait_group 0;");
        }
        __syncthreads();
    }

    // ---- epilogue prep ----
    if (GATE) {
        if (tid < 128) { srow[tid] = bias[tid]; sw2[tid] = W2[tid]; }
    } else {
        if (tid < 128) {
            int gr = rowBase + tid;
            if (gr < n) {
                int s = load_idx(idx, gr);
                sidx[tid] = s;
                srow[tid] = g_e[gr] / fmaxf(g_segsum[s], 1e-16f);
            } else { sidx[tid] = -1; srow[tid] = 0.f; }
        }
    }

    // stage C tile into fp32 smem (reuse pipeline smem)
    float* Tsm = (float*)sm;
#pragma unroll
    for (int mt = 0; mt < 2; mt++)
#pragma unroll
        for (int nt = 0; nt < 8; nt++) {
            int r0 = warpRow + mt * 16 + (lane >> 2);
            int c0 = warpCol + nt * 8 + ((lane & 3) << 1);
            Tsm[r0 * TSST + c0]           = acc[mt][nt][0];
            Tsm[r0 * TSST + c0 + 1]       = acc[mt][nt][1];
            Tsm[(r0 + 8) * TSST + c0]     = acc[mt][nt][2];
            Tsm[(r0 + 8) * TSST + c0 + 1] = acc[mt][nt][3];
        }
    __syncthreads();

    if (GATE) {
        if (tid < 128) {
            int gr = rowBase + tid;
            if (gr < n) {
                float g = b2[0];
#pragma unroll 8
                for (int j = 0; j < HID; j++)
                    g = fmaf(fmaxf(Tsm[tid * TSST + j] + srow[j], 0.f), sw2[j], g);
                float e = expf(g);       // gate is O(1): no max-shift needed
                g_e[gr] = e;
                int s = load_idx(idx, gr);
                atomicAdd(&g_segsum[s], e);
            }
        }
    } else {
        // 256 threads: 128 columns x 2 row-halves, sorted segmented scan
        int c = tid & 127;
        int rStart = (tid >> 7) * 64;
        float btc = bias[nBase + c];
        float a = 0.f;
        int prev = -1;
        for (int r = rStart; r < rStart + 64; r++) {
            int s = sidx[r];
            if (s < 0) break;
            if (s != prev) {
                if (prev >= 0)
                    atomicAdd(&out[(size_t)prev * OUT_CH + nBase + c], a);
                a = 0.f;
                prev = s;
            }
            a = fmaf(fmaxf(Tsm[r * TSST + c] + btc, 0.f), srow[r], a);
        }
        if (prev >= 0)
            atomicAdd(&out[(size_t)prev * OUT_CH + nBase + c], a);
    }
}

// ---------------- launch -----------------------------------------------------
extern "C" void kernel_launch(void* const* d_in, const int* in_sizes, int n_in,
                              void* d_out, int out_size)
{
    const float* X   = (const float*)d_in[0];
    const void*  idx = d_in[1];
    int base = (n_in >= 9 && in_sizes[2] <= 16) ? 3 : 2;
    const float* W1 = (const float*)d_in[base + 0];
    const float* b1 = (const float*)d_in[base + 1];
    const float* W2 = (const float*)d_in[base + 2];
    const float* b2 = (const float*)d_in[base + 3];
    const float* Wt = (const float*)d_in[base + 4];
    const float* bt = (const float*)d_in[base + 5];

    const int n = in_sizes[0] / IN_CH;
    float* out = (float*)d_out;

    cudaFuncSetAttribute(mma_gemm_kernel<1>,
                         cudaFuncAttributeMaxDynamicSharedMemorySize, SMEM_BYTES);
    cudaFuncSetAttribute(mma_gemm_kernel<0>,
                         cudaFuncAttributeMaxDynamicSharedMemorySize, SMEM_BYTES);

    cudaMemsetAsync(d_out, 0, (size_t)out_size * sizeof(float), 0);
    detect_idx_kernel<<<1, 32>>>(idx, n);
    init_seg_kernel<<<(S_MAX + 255) / 256, 256>>>();
    convert_w_kernel<<<(IN_CH * OUT_CH + 255) / 256, 256>>>(W1, Wt);

    const int nTiles = (n + 127) / 128;
    mma_gemm_kernel<1><<<dim3(nTiles, 1), 256, SMEM_BYTES>>>(
        X, idx, b1, W2, b2, nullptr, n);
    mma_gemm_kernel<0><<<dim3(nTiles, 2), 256, SMEM_BYTES>>>(
        X, idx, bt, nullptr, nullptr, out, n);
}